// round 14
// baseline (speedup 1.0000x reference)
#include <cuda_runtime.h>

// ---------------------------------------------------------------------------
// SynthMorphLoss fused single-kernel:
//   blocks [0,144):     diffusion, cp.async-pipelined z-march of 4-row strips
//   blocks [144,1000):  26-bin histograms of both int32 label maps
//   last block to finish: dice + means -> out[3], reset scratch.
// Inputs: d_in[0] int32[6881280], d_in[1] int32[6881280],
//         d_in[2] float32[20643840] = [1,3,160,192,224]
// Output: float32[3] = (total, similarity, smoothness)
// ---------------------------------------------------------------------------

#define T      256
#define DBLK   144           // 3 channels * 48 y-strips
#define HBLK   856
#define GRID   (DBLK + HBLK)
#define NBINS  26
#define NW     21            // 3 types * 7 packed words per thread
#define PLANE  10752         // float4 per (c,z) plane = 192*56
#define NSTG   7             // smem ring slots
#define STGE   280           // float4 per stage = 5 rows * 56

__device__ unsigned g_hist[3 * NBINS];  // [fixed_vol | moving_vol | inter]
__device__ double   g_sums[3];          // [sum dz^2, sum dy^2, sum dx^2]
__device__ unsigned g_done;

struct SmemU {
    union {
        unsigned hist[NW * T];          // 21504 B (hist blocks)
        float4   st[NSTG][STGE];        // 31360 B (diff blocks)
    } u;
    float r[3][T / 32];
    int   slast;
};

__device__ __forceinline__ void cpa16(unsigned d, const float4* g) {
    asm volatile("cp.async.cg.shared.global [%0], [%1], 16;" :: "r"(d), "l"(g));
}

__global__ __launch_bounds__(T) void fused_k(const int* __restrict__ f,
                                             const int* __restrict__ m,
                                             const float* __restrict__ vf,
                                             float* __restrict__ out,
                                             int n4lab) {
    __shared__ SmemU sm;
    const int tid = threadIdx.x;
    const int bid = blockIdx.x;

    if (bid < DBLK) {
        // ========== diffusion: cp.async ring, one strip per block ==========
        const float4* v4 = (const float4*)vf;
        const int c  = bid / 48;
        const int y0 = (bid - c * 48) * 4;          // strip rows y0..y0+3

        // loader mapping: element e -> (row e/56, x e%56), row clamped to 191
        const int r1 = tid / 56, x1 = tid - r1 * 56;
        const int off1 = min(y0 + r1, 191) * 56 + x1;
        const int e2 = tid + 256;                   // only threads 0..23
        const int r2 = e2 / 56, x2 = e2 - r2 * 56;
        const int off2 = min(y0 + r2, 191) * 56 + x2;
        const bool has2 = (tid < 24);

        const unsigned sbase =
            (unsigned)__cvta_generic_to_shared(&sm.u.st[0][0]);
        const int pb0 = c * 160 * PLANE;

        auto issue = [&](int z, int slot) {
            const float4* base = v4 + pb0 + z * PLANE;
            cpa16(sbase + (unsigned)(slot * STGE + tid) * 16u, base + off1);
            if (has2)
                cpa16(sbase + (unsigned)(slot * STGE + e2) * 16u, base + off2);
            asm volatile("cp.async.commit_group;");
        };

        issue(0, 0); issue(1, 1); issue(2, 2); issue(3, 3);   // prologue

        // compute-cell constants (cells are threads 0..223; cell idx == tid)
        const float wy = (y0 + r1 < 191) ? 1.f : 0.f;
        const float wx = (x1 < 55) ? 1.f : 0.f;
        const int   xo = (x1 < 55) ? 1 : 0;
        float sx = 0.f, sy = 0.f, sz = 0.f;

        auto xy = [&](const float4& v, int slot) {
            float d0 = v.y - v.x, d1 = v.z - v.y, d2 = v.w - v.z;
            sx += d0 * d0 + d1 * d1 + d2 * d2;
            float nx = sm.u.st[slot][tid + xo].x;
            float dd = nx - v.w;
            sx += wx * (dd * dd);
            float4 u = sm.u.st[slot][tid + 56];
            float a = u.x - v.x, b = u.y - v.y,
                  c2 = u.z - v.z, e = u.w - v.w;
            sy += wy * (a * a + b * b + c2 * c2 + e * e);
        };
        auto zsq = [](const float4& A, const float4& B) {
            float a = B.x - A.x, b = B.y - A.y,
                  c2 = B.z - A.z, e = B.w - A.w;
            return a * a + b * b + c2 * c2 + e * e;
        };

        int sA = 0;                                 // slot of plane 2i
        for (int i = 0; i < 80; i++) {
            // stages 0..2i+3 issued; oldest 2i+2 done once <=2 pending
            asm volatile("cp.async.wait_group 2;");
            __syncthreads();
            int sB = sA + 1; if (sB >= NSTG) sB -= NSTG;
            int sP = sA - 1; if (sP < 0)     sP += NSTG;

            if (tid < 224) {
                float4 vA = sm.u.st[sA][tid];
                float4 vB = sm.u.st[sB][tid];
                xy(vA, sA);
                xy(vB, sB);
                if (i > 0) {                         // pair (2i-1, 2i)
                    float4 vP = sm.u.st[sP][tid];
                    sz += zsq(vP, vA);
                }
                sz += zsq(vA, vB);                   // pair (2i, 2i+1)
            }
            // write slots sA+4, sA+5 are disjoint from read slots sP,sA,sB
            int z1 = 2 * i + 4;
            if (z1 < 160) {
                int s1 = sA + 4; if (s1 >= NSTG) s1 -= NSTG;
                issue(z1, s1);
                int z2 = z1 + 1;
                if (z2 < 160) {
                    int s2 = sA + 5; if (s2 >= NSTG) s2 -= NSTG;
                    issue(z2, s2);
                }
            }
            sA += 2; if (sA >= NSTG) sA -= NSTG;
        }

        // block reduce -> 3 double atomics (threads 224..255 contribute 0)
        #pragma unroll
        for (int o = 16; o > 0; o >>= 1) {
            sz += __shfl_down_sync(0xffffffffu, sz, o);
            sy += __shfl_down_sync(0xffffffffu, sy, o);
            sx += __shfl_down_sync(0xffffffffu, sx, o);
        }
        int lane = tid & 31, w = tid >> 5;
        if (lane == 0) { sm.r[0][w] = sz; sm.r[1][w] = sy; sm.r[2][w] = sx; }
        __syncthreads();
        if (tid == 0) {
            float tz = 0.f, ty = 0.f, tx = 0.f;
            #pragma unroll
            for (int k = 0; k < T / 32; k++) {
                tz += sm.r[0][k]; ty += sm.r[1][k]; tx += sm.r[2][k];
            }
            atomicAdd(&g_sums[0], (double)tz);
            atomicAdd(&g_sums[1], (double)ty);
            atomicAdd(&g_sums[2], (double)tx);
            __threadfence();
        }
    } else {
        // ================= histogram partition (R5-proven) =================
        unsigned* s = sm.u.hist;
        #pragma unroll
        for (int w = 0; w < NW; w++) s[w * T + tid] = 0u;
        __syncthreads();

        const int4* f4 = (const int4*)f;
        const int4* m4 = (const int4*)m;
        const int step = HBLK * T;

        auto proc = [&](int fa, int mb) {
            unsigned fu = min((unsigned)fa, 25u);
            unsigned mu = min((unsigned)mb, 25u);
            s[(fu >> 2) * T + tid]        += 1u << ((fu & 3u) * 8u);
            s[(7u + (mu >> 2)) * T + tid] += 1u << ((mu & 3u) * 8u);
            if (fu == mu)
                s[(14u + (fu >> 2)) * T + tid] += 1u << ((fu & 3u) * 8u);
        };

        int i = (bid - DBLK) * T + tid;   // always < n4lab (856*256 < n4lab)
        for (; i + step < n4lab; i += 2 * step) {
            int4 a0 = f4[i],        b0 = m4[i];
            int4 a1 = f4[i + step], b1 = m4[i + step];
            proc(a0.x, b0.x); proc(a0.y, b0.y); proc(a0.z, b0.z); proc(a0.w, b0.w);
            proc(a1.x, b1.x); proc(a1.y, b1.y); proc(a1.z, b1.z); proc(a1.w, b1.w);
        }
        if (i < n4lab) {
            int4 a = f4[i], b = m4[i];
            proc(a.x, b.x); proc(a.y, b.y); proc(a.z, b.z); proc(a.w, b.w);
        }
        __syncthreads();

        // block reduce: 21 threads, dual-lane 16-bit accumulation.
        // per-thread byte counts <= 32; 16-bit lane sums <= 8192 < 65535.
        if (tid < NW) {
            const unsigned* row = &s[tid * T];
            unsigned a02 = 0u, a13 = 0u;
            #pragma unroll 8
            for (int kk = 0; kk < T; kk++) {
                unsigned wv = row[(kk + tid * 12) & (T - 1)];
                a02 += wv & 0x00FF00FFu;
                a13 += (wv >> 8) & 0x00FF00FFu;
            }
            int type = tid / 7, wi = tid - type * 7;
            int b0 = wi * 4;
            unsigned c0 = a02 & 0xFFFFu, c1 = a13 & 0xFFFFu;
            unsigned c2 = a02 >> 16,     c3 = a13 >> 16;
            if (b0 + 0 < NBINS && c0) atomicAdd(&g_hist[type * NBINS + b0 + 0], c0);
            if (b0 + 1 < NBINS && c1) atomicAdd(&g_hist[type * NBINS + b0 + 1], c1);
            if (b0 + 2 < NBINS && c2) atomicAdd(&g_hist[type * NBINS + b0 + 2], c2);
            if (b0 + 3 < NBINS && c3) atomicAdd(&g_hist[type * NBINS + b0 + 3], c3);
            __threadfence();
        }
    }

    // ================= completion + finalize in last block =================
    __syncthreads();
    if (tid == 0) {
        unsigned prev = atomicAdd(&g_done, 1u);
        sm.slast = (prev == (unsigned)(GRID - 1));
    }
    __syncthreads();
    if (!sm.slast) return;
    __threadfence();                    // acquire: all blocks' REDs visible

    if (tid < 32) {
        volatile unsigned* vh = g_hist;
        volatile double*   vs = g_sums;
        double term = 0.0;
        if (tid >= 1 && tid < 26) {     // class 0 ignored; 25 parallel fp64 divs
            double inter = (double)vh[2 * NBINS + tid];
            double fv    = (double)vh[tid];
            double mv    = (double)vh[NBINS + tid];
            term = (2.0 * inter + 1e-5) / (fv + mv + 1e-5);
        }
        #pragma unroll
        for (int o = 16; o > 0; o >>= 1)
            term += __shfl_down_sync(0xffffffffu, term, o);
        if (tid == 0) {
            double sim = 1.0 - term / 25.0;
            // denominators: 3*159*192*224, 3*160*191*224, 3*160*192*223
            double smv = (vs[0] / 20514816.0 +
                          vs[1] / 20536320.0 +
                          vs[2] / 20551680.0) / 3.0;
            out[0] = (float)(sim + smv);
            out[1] = (float)sim;
            out[2] = (float)smv;
        }
    }
    __syncthreads();                    // reads done before resets
    if (tid < 3 * NBINS) g_hist[tid] = 0u;      // self-clean for next replay
    if (tid >= 96 && tid < 99) g_sums[tid - 96] = 0.0;
    if (tid == 128) g_done = 0u;
}

// ---------------------------------------------------------------------------
extern "C" void kernel_launch(void* const* d_in, const int* in_sizes, int n_in,
                              void* d_out, int out_size) {
    const int*   fixedmap = (const int*)d_in[0];
    const int*   moving   = (const int*)d_in[1];
    const float* vf       = (const float*)d_in[2];
    float*       out      = (float*)d_out;

    int n4lab = in_sizes[0] / 4;   // 1,720,320 int4

    fused_k<<<GRID, T>>>(fixedmap, moving, vf, out, n4lab);
}

// round 16
// speedup vs baseline: 1.0792x; 1.0792x over previous
#include <cuda_runtime.h>

// ---------------------------------------------------------------------------
// SynthMorphLoss fused single-kernel, WARP-specialized inside every block:
//   warps 0-4 (tid 0..159):   diffusion regularizer, z-marching columns
//   warps 5-7 (tid 160..255): 26-bin histograms of both int32 label maps
//   last block to finish: dice + means -> out[3], reset scratch.
// Every SMSP holds both stream flavors for the whole kernel duration, so the
// hist warps' SMEM-chain execution hides the diff warps' DRAM stalls and
// vice versa. One wave: 1184 blocks x 256 thr, <=32 regs, ~8.2 KB smem.
// Inputs: d_in[0] int32[6881280], d_in[1] int32[6881280],
//         d_in[2] float32[20643840] = [1,3,160,192,224]
// Output: float32[3] = (total, similarity, smoothness)
// ---------------------------------------------------------------------------

#define T       256
#define GRID    1184        // 148 SMs x 8 blocks -> one wave
#define NBINS   26
#define NW      21          // 3 types * 7 packed words per hist thread
#define HT      96          // hist threads per block (warps 5..7)
#define HSTEP   (GRID * HT) // 113,664
#define PL      10752       // z-plane stride in float4 (192*56)
#define CHUNK   32          // z-planes per diffusion unit (160 = 5*32)
#define NUNITS  161280      // 3ch * 5 chunks * 192 y * 56 x4
#define DW      5           // diffusion warps per block

__device__ unsigned g_hist[3 * NBINS];  // [fixed_vol | moving_vol | inter]
__device__ double   g_sums[3];          // [sum dz^2, sum dy^2, sum dx^2]
__device__ unsigned g_done;

__global__ __launch_bounds__(T) void fused_k(const int* __restrict__ f,
                                             const int* __restrict__ m,
                                             const float* __restrict__ vf,
                                             float* __restrict__ out,
                                             int n4lab) {
    __shared__ unsigned s[NW * HT];     // 8064 B packed hist counters
    __shared__ float    r[3][DW];
    __shared__ int      slast;
    const int tid = threadIdx.x;
    const int bid = blockIdx.x;
    const int wid = tid >> 5;

    for (int j = tid; j < NW * HT; j += T) s[j] = 0u;
    __syncthreads();

    if (wid >= DW) {
        // ============ histogram warps (tid 160..255, ht 0..95) ============
        const int ht = tid - DW * 32;
        const int4* f4 = (const int4*)f;
        const int4* m4 = (const int4*)m;

        auto proc = [&](int fa, int mb) {
            unsigned fu = min((unsigned)fa, 25u);
            unsigned mu = min((unsigned)mb, 25u);
            s[(fu >> 2) * HT + ht]        += 1u << ((fu & 3u) * 8u);
            s[(7u + (mu >> 2)) * HT + ht] += 1u << ((mu & 3u) * 8u);
            if (fu == mu)
                s[(14u + (fu >> 2)) * HT + ht] += 1u << ((fu & 3u) * 8u);
        };

        // 2x unrolled grid-stride: 4 LDG.128 (16 lines) in flight per warp
        int i = bid * HT + ht;          // < HSTEP <= n4lab
        for (; i + HSTEP < n4lab; i += 2 * HSTEP) {
            int4 a0 = f4[i],         b0 = m4[i];
            int4 a1 = f4[i + HSTEP], b1 = m4[i + HSTEP];
            proc(a0.x, b0.x); proc(a0.y, b0.y); proc(a0.z, b0.z); proc(a0.w, b0.w);
            proc(a1.x, b1.x); proc(a1.y, b1.y); proc(a1.z, b1.z); proc(a1.w, b1.w);
        }
        if (i < n4lab) {
            int4 a = f4[i], b = m4[i];
            proc(a.x, b.x); proc(a.y, b.y); proc(a.z, b.z); proc(a.w, b.w);
        }
    } else {
        // ======== diffusion warps (tid 0..159): z-marching columns ========
        // unit u -> (c, zc, y, x4); at most one unit per thread.
        const float4* v4 = (const float4*)vf;
        const int u = bid * (DW * 32) + tid;
        float sx = 0.f, sy = 0.f, sz = 0.f;

        if (u < NUNITS) {
            int x4 = u % 56;
            int t  = u / 56;
            int y  = t % 192;
            int cz = t / 192;           // 0..14 = c*5 + zc
            int zc = cz % 5;
            int c  = cz / 5;
            int idx = ((c * 160 + zc * CHUNK) * 192 + y) * 56 + x4;

            const bool do_y = (y < 191);
            const bool do_x = (x4 < 55);
            const int zmax = (zc < 4) ? CHUNK : (CHUNK - 1);

            auto xyp = [&](const float4& v, int id) {
                float d0 = v.y - v.x, d1 = v.z - v.y, d2 = v.w - v.z;
                sx += d0 * d0 + d1 * d1 + d2 * d2;
                if (do_x) {
                    float nx = __ldg(&vf[4 * id + 4]);
                    float d = nx - v.w;
                    sx += d * d;
                }
                if (do_y) {
                    float4 uu = v4[id + 56];
                    float a = uu.x - v.x, b = uu.y - v.y,
                          cc = uu.z - v.z, e = uu.w - v.w;
                    sy += a * a + b * b + cc * cc + e * e;
                }
            };

            float4 p = v4[idx];
            xyp(p, idx);                 // plane z0
            #pragma unroll 4
            for (int k = 1; k <= zmax; k++) {
                idx += PL;
                float4 cu = v4[idx];
                float a = cu.x - p.x, b = cu.y - p.y,
                      cc = cu.z - p.z, e = cu.w - p.w;
                sz += a * a + b * b + cc * cc + e * e;
                if (k < CHUNK) xyp(cu, idx);  // crossing plane owned by next unit
                p = cu;
            }
        }

        // warp reduce; lane 0 stores partials
        #pragma unroll
        for (int o = 16; o > 0; o >>= 1) {
            sz += __shfl_down_sync(0xffffffffu, sz, o);
            sy += __shfl_down_sync(0xffffffffu, sy, o);
            sx += __shfl_down_sync(0xffffffffu, sx, o);
        }
        if ((tid & 31) == 0) { r[0][wid] = sz; r[1][wid] = sy; r[2][wid] = sx; }
    }

    __syncthreads();

    // ---- hist block-reduce: 21 threads, dual-lane 16-bit accumulation ----
    // per-thread byte counts <= 64; 16-bit lane sums <= 96*64 = 6144.
    if (tid < NW) {
        const unsigned* row = &s[tid * HT];
        unsigned a02 = 0u, a13 = 0u;
        #pragma unroll 4
        for (int kk = 0; kk < HT; kk++) {
            int k = kk + tid * 5;               // skew -> spread banks
            if (k >= HT) k -= HT;
            if (k >= HT) k -= HT;
            unsigned wv = row[k];
            a02 += wv & 0x00FF00FFu;
            a13 += (wv >> 8) & 0x00FF00FFu;
        }
        int type = tid / 7, wi = tid - type * 7;
        int b0 = wi * 4;
        unsigned c0 = a02 & 0xFFFFu, c1 = a13 & 0xFFFFu;
        unsigned c2 = a02 >> 16,     c3 = a13 >> 16;
        if (b0 + 0 < NBINS && c0) atomicAdd(&g_hist[type * NBINS + b0 + 0], c0);
        if (b0 + 1 < NBINS && c1) atomicAdd(&g_hist[type * NBINS + b0 + 1], c1);
        if (b0 + 2 < NBINS && c2) atomicAdd(&g_hist[type * NBINS + b0 + 2], c2);
        if (b0 + 3 < NBINS && c3) atomicAdd(&g_hist[type * NBINS + b0 + 3], c3);
        __threadfence();
    }
    // ---- diffusion block total: 3 double atomics ----
    if (tid == 32) {
        float tz = 0.f, ty = 0.f, tx = 0.f;
        #pragma unroll
        for (int k = 0; k < DW; k++) { tz += r[0][k]; ty += r[1][k]; tx += r[2][k]; }
        atomicAdd(&g_sums[0], (double)tz);
        atomicAdd(&g_sums[1], (double)ty);
        atomicAdd(&g_sums[2], (double)tx);
        __threadfence();
    }

    // ================= completion + finalize in last block =================
    __syncthreads();
    if (tid == 0) {
        unsigned prev = atomicAdd(&g_done, 1u);
        slast = (prev == (unsigned)(GRID - 1));
    }
    __syncthreads();
    if (!slast) return;
    __threadfence();                    // acquire: all blocks' REDs visible

    if (tid < 32) {
        volatile unsigned* vh = g_hist;
        volatile double*   vs = g_sums;
        double term = 0.0;
        if (tid >= 1 && tid < 26) {     // class 0 ignored; 25 parallel fp64 divs
            double inter = (double)vh[2 * NBINS + tid];
            double fv    = (double)vh[tid];
            double mv    = (double)vh[NBINS + tid];
            term = (2.0 * inter + 1e-5) / (fv + mv + 1e-5);
        }
        #pragma unroll
        for (int o = 16; o > 0; o >>= 1)
            term += __shfl_down_sync(0xffffffffu, term, o);
        if (tid == 0) {
            double sim = 1.0 - term / 25.0;
            // denominators: 3*159*192*224, 3*160*191*224, 3*160*192*223
            double sm = (vs[0] / 20514816.0 +
                         vs[1] / 20536320.0 +
                         vs[2] / 20551680.0) / 3.0;
            out[0] = (float)(sim + sm);
            out[1] = (float)sim;
            out[2] = (float)sm;
        }
    }
    __syncthreads();                    // reads done before resets
    if (tid < 3 * NBINS) g_hist[tid] = 0u;      // self-clean for next replay
    if (tid >= 96 && tid < 99) g_sums[tid - 96] = 0.0;
    if (tid == 128) g_done = 0u;
}

// ---------------------------------------------------------------------------
extern "C" void kernel_launch(void* const* d_in, const int* in_sizes, int n_in,
                              void* d_out, int out_size) {
    const int*   fixedmap = (const int*)d_in[0];
    const int*   moving   = (const int*)d_in[1];
    const float* vf       = (const float*)d_in[2];
    float*       out      = (float*)d_out;

    int n4lab = in_sizes[0] / 4;   // 1,720,320 int4

    fused_k<<<GRID, T>>>(fixedmap, moving, vf, out, n4lab);
}